// round 8
// baseline (speedup 1.0000x reference)
#include <cuda_runtime.h>
#include <math.h>

#define N_NODES 100000
#define N_EDGES 1600000
#define D_FEAT  64
#define EPS     1e-7f
#define FULL    0xffffffffu

// Scratch
__device__ float g_inv[N_NODES];          // 1 / ||x_i||
__device__ int   g_col[N_EDGES];          // edge_col as int32
__device__ int   g_rowptr[N_NODES + 1];

// ---------------------------------------------------------------------------
__device__ __forceinline__ int detect_is64(const unsigned int* ec_raw)
{
    unsigned acc = 0;
    #pragma unroll
    for (int i = 1; i < 16; i += 2) acc |= ec_raw[i];
    return acc == 0u;
}

__device__ __forceinline__ int get_idx(const void* p, int e, int is64)
{
    if (is64) return (int)((const long long*)p)[e];
    return ((const int*)p)[e];
}

// ---------------------------------------------------------------------------
// Prep kernel: three jobs via block-range split.
// ---------------------------------------------------------------------------
#define B_NORM 6250     // N_NODES*16 / 256
#define B_COL  6250     // N_EDGES / 256
#define B_ROW  391      // ceil((N_NODES+1)/256)

__global__ void __launch_bounds__(256)
prep_kernel(const float4* __restrict__ x4,
            const void* __restrict__ er,
            const void* __restrict__ ec)
{
    int b = blockIdx.x;
    if (b < B_NORM) {
        int t    = b * 256 + threadIdx.x;
        int node = t >> 4;
        int sub  = t & 15;
        if (node >= N_NODES) return;
        float4 a = x4[node * 16 + sub];
        float s = a.x * a.x + a.y * a.y + a.z * a.z + a.w * a.w;
        #pragma unroll
        for (int o = 8; o; o >>= 1) s += __shfl_xor_sync(FULL, s, o);
        if (sub == 0) g_inv[node] = rsqrtf(s);
    } else if (b < B_NORM + B_COL) {
        int e = (b - B_NORM) * 256 + threadIdx.x;
        if (e >= N_EDGES) return;
        int is64 = detect_is64((const unsigned int*)ec);
        g_col[e] = get_idx(ec, e, is64);
    } else {
        int i = (b - B_NORM - B_COL) * 256 + threadIdx.x;
        if (i > N_NODES) return;
        int is64 = detect_is64((const unsigned int*)ec);
        int lo = 0, hi = N_EDGES;
        while (lo < hi) {
            int mid = (lo + hi) >> 1;
            if (get_idx(er, mid, is64) < i) lo = mid + 1; else hi = mid;
        }
        g_rowptr[i] = lo;
    }
}

// ---------------------------------------------------------------------------
// Fused sim + softmax + SPMM. TWO WARPS PER ROW (alternating 32-edge chunks).
// Within a warp: lane = (group g 0..3) x (feature f 0..7); 4 edges in flight,
// each edge row = 8 lanes x two float4 (two 128B lines). w = exp(beta*(cos-1))
// is shift-invariant softmax with arg<=0, so warp partials combine by plain
// addition -> cross-warp combine via smem.
// ---------------------------------------------------------------------------
__global__ void __launch_bounds__(256)
fused_row_kernel(const float4* __restrict__ x4,
                 const float* __restrict__ beta,
                 float4* __restrict__ out4)
{
    __shared__ float s_acc[8][8][8];      // [warpInBlock][f][8 floats]
    __shared__ float s_wsum[8];

    int gw   = (blockIdx.x * blockDim.x + threadIdx.x) >> 5;  // global warp
    int row  = gw >> 1;
    int half = gw & 1;
    if (row >= N_NODES) return;
    int lane = threadIdx.x & 31;
    int wib  = (threadIdx.x >> 5);        // warp in block
    int g = lane >> 3;                    // edge slot (0..3)
    int f = lane & 7;                     // feature slice

    int s = g_rowptr[row];
    int n = g_rowptr[row + 1] - s;

    float4 xr0 = x4[row * 16 + f];
    float4 xr1 = x4[row * 16 + 8 + f];
    float  bv  = beta[0];
    float  bs  = bv * g_inv[row];

    float4 acc0 = make_float4(0.f, 0.f, 0.f, 0.f);
    float4 acc1 = make_float4(0.f, 0.f, 0.f, 0.f);
    float  wsum = 0.f;

    const int* __restrict__ col = g_col;

    // this warp's chunks: base = half*32, half*32+64, ...
    for (int base = half * 32; base < n; base += 64) {
        int rem = n - base;
        int cnt = rem < 32 ? rem : 32;

        int   myc   = (lane < cnt) ? col[s + base + lane] : row;
        float myinv = g_inv[myc];
        int iters = (cnt + 3) >> 2;

        #pragma unroll 2
        for (int it = 0; it < iters; ++it) {
            int   src   = it * 4 + g;
            int   c     = __shfl_sync(FULL, myc, src);
            float invnc = __shfl_sync(FULL, myinv, src);
            bool  valid = src < cnt;

            float4 b0 = x4[c * 16 + f];
            float4 b1 = x4[c * 16 + 8 + f];

            float d = b0.x * xr0.x + b0.y * xr0.y + b0.z * xr0.z + b0.w * xr0.w
                    + b1.x * xr1.x + b1.y * xr1.y + b1.z * xr1.z + b1.w * xr1.w;
            d += __shfl_xor_sync(FULL, d, 1);
            d += __shfl_xor_sync(FULL, d, 2);
            d += __shfl_xor_sync(FULL, d, 4);

            float w = __expf(fmaf(bs * invnc, d, -bv));
            w = valid ? w : 0.f;

            wsum  += w;
            acc0.x = fmaf(w, b0.x, acc0.x);
            acc0.y = fmaf(w, b0.y, acc0.y);
            acc0.z = fmaf(w, b0.z, acc0.z);
            acc0.w = fmaf(w, b0.w, acc0.w);
            acc1.x = fmaf(w, b1.x, acc1.x);
            acc1.y = fmaf(w, b1.y, acc1.y);
            acc1.z = fmaf(w, b1.z, acc1.z);
            acc1.w = fmaf(w, b1.w, acc1.w);
        }
    }

    // intra-warp: reduce the 4 edge-groups
    #pragma unroll
    for (int o = 8; o <= 16; o <<= 1) {
        acc0.x += __shfl_xor_sync(FULL, acc0.x, o);
        acc0.y += __shfl_xor_sync(FULL, acc0.y, o);
        acc0.z += __shfl_xor_sync(FULL, acc0.z, o);
        acc0.w += __shfl_xor_sync(FULL, acc0.w, o);
        acc1.x += __shfl_xor_sync(FULL, acc1.x, o);
        acc1.y += __shfl_xor_sync(FULL, acc1.y, o);
        acc1.z += __shfl_xor_sync(FULL, acc1.z, o);
        acc1.w += __shfl_xor_sync(FULL, acc1.w, o);
        wsum   += __shfl_xor_sync(FULL, wsum,   o);
    }

    // cross-warp combine via smem (warp pair 2k / 2k+1 share a row)
    if (g == 0) {
        s_acc[wib][f][0] = acc0.x;  s_acc[wib][f][1] = acc0.y;
        s_acc[wib][f][2] = acc0.z;  s_acc[wib][f][3] = acc0.w;
        s_acc[wib][f][4] = acc1.x;  s_acc[wib][f][5] = acc1.y;
        s_acc[wib][f][6] = acc1.z;  s_acc[wib][f][7] = acc1.w;
        if (f == 0) s_wsum[wib] = wsum;
    }
    __syncthreads();

    if (half == 0 && g == 0) {
        int pw = wib + 1;                 // partner warp
        float tw = wsum + s_wsum[pw];
        float inv = (n > 0) ? (1.f / tw) : 0.f;
        float4 o0, o1;
        o0.x = (acc0.x + s_acc[pw][f][0]) * inv;
        o0.y = (acc0.y + s_acc[pw][f][1]) * inv;
        o0.z = (acc0.z + s_acc[pw][f][2]) * inv;
        o0.w = (acc0.w + s_acc[pw][f][3]) * inv;
        o1.x = (acc1.x + s_acc[pw][f][4]) * inv;
        o1.y = (acc1.y + s_acc[pw][f][5]) * inv;
        o1.z = (acc1.z + s_acc[pw][f][6]) * inv;
        o1.w = (acc1.w + s_acc[pw][f][7]) * inv;
        out4[row * 16 + f]     = o0;
        out4[row * 16 + 8 + f] = o1;
    }
}

// ---------------------------------------------------------------------------
extern "C" void kernel_launch(void* const* d_in, const int* in_sizes, int n_in,
                              void* d_out, int out_size)
{
    const float4* x    = 0;
    const float*  beta = 0;
    const void*   er   = 0;
    const void*   ec   = 0;
    for (int i = 0; i < n_in; ++i) {
        long long sz = in_sizes[i];
        if (sz == (long long)N_NODES * D_FEAT) x = (const float4*)d_in[i];
        else if (sz == 1)                      beta = (const float*)d_in[i];
        else if (sz == N_EDGES) {
            if (!er) er = d_in[i]; else ec = d_in[i];
        }
    }
    float4* out = (float4*)d_out;

    prep_kernel<<<B_NORM + B_COL + B_ROW, 256>>>(x, er, ec);

    {   // two warps per row
        long long total = (long long)N_NODES * 2 * 32;
        int blocks = (int)((total + 255) / 256);
        fused_row_kernel<<<blocks, 256>>>(x, beta, out);
    }
}

// round 9
// speedup vs baseline: 1.4322x; 1.4322x over previous
#include <cuda_runtime.h>
#include <math.h>

#define N_NODES 100000
#define N_EDGES 1600000
#define D_FEAT  64
#define EPS     1e-7f
#define FULL    0xffffffffu

// Scratch
__device__ float g_inv[N_NODES];          // 1 / ||x_i||
__device__ int   g_col[N_EDGES];          // edge_col as int32
__device__ int   g_rowptr[N_NODES + 1];

// ---------------------------------------------------------------------------
__device__ __forceinline__ int detect_is64(const unsigned int* ec_raw)
{
    unsigned acc = 0;
    #pragma unroll
    for (int i = 1; i < 16; i += 2) acc |= ec_raw[i];
    return acc == 0u;
}

__device__ __forceinline__ int get_idx(const void* p, int e, int is64)
{
    if (is64) return (int)((const long long*)p)[e];
    return ((const int*)p)[e];
}

// ---------------------------------------------------------------------------
// Prep kernel: three jobs via block-range split.
// ---------------------------------------------------------------------------
#define B_NORM 6250     // N_NODES*16 / 256
#define B_COL  6250     // N_EDGES / 256
#define B_ROW  391      // ceil((N_NODES+1)/256)

__global__ void __launch_bounds__(256)
prep_kernel(const float4* __restrict__ x4,
            const void* __restrict__ er,
            const void* __restrict__ ec)
{
    int b = blockIdx.x;
    if (b < B_NORM) {
        int t    = b * 256 + threadIdx.x;
        int node = t >> 4;
        int sub  = t & 15;
        if (node >= N_NODES) return;
        float4 a = x4[node * 16 + sub];
        float s = a.x * a.x + a.y * a.y + a.z * a.z + a.w * a.w;
        #pragma unroll
        for (int o = 8; o; o >>= 1) s += __shfl_xor_sync(FULL, s, o);
        if (sub == 0) g_inv[node] = rsqrtf(s);
    } else if (b < B_NORM + B_COL) {
        int e = (b - B_NORM) * 256 + threadIdx.x;
        if (e >= N_EDGES) return;
        int is64 = detect_is64((const unsigned int*)ec);
        g_col[e] = get_idx(ec, e, is64);
    } else {
        int i = (b - B_NORM - B_COL) * 256 + threadIdx.x;
        if (i > N_NODES) return;
        int is64 = detect_is64((const unsigned int*)ec);
        int lo = 0, hi = N_EDGES;
        while (lo < hi) {
            int mid = (lo + hi) >> 1;
            if (get_idx(er, mid, is64) < i) lo = mid + 1; else hi = mid;
        }
        g_rowptr[i] = lo;
    }
}

// ---------------------------------------------------------------------------
// Fused sim + softmax + SPMM. ONE WARP PER ROW.
// Lane = (group g 0..3) x (feature f 0..7): 4 edges per iteration, each edge
// row = 8 lanes x two float4 (two 128B lines). Edge index + inv-norm come
// from broadcast loads (same address across the 8 lanes of a group) instead
// of shuffles, so the address chain is hoistable and deeply pipelined.
// Softmax as w = exp(beta*(cos-1)): shift-invariant, arg<=0, no running max.
// ---------------------------------------------------------------------------
__global__ void __launch_bounds__(256)
fused_row_kernel(const float4* __restrict__ x4,
                 const float* __restrict__ beta,
                 float4* __restrict__ out4)
{
    int warp = (blockIdx.x * blockDim.x + threadIdx.x) >> 5;
    if (warp >= N_NODES) return;
    int lane = threadIdx.x & 31;
    int g = lane >> 3;                    // edge slot within iteration
    int f = lane & 7;                     // feature slice

    int row = warp;
    int s = g_rowptr[row];
    int n = g_rowptr[row + 1] - s;

    float4 xr0 = x4[row * 16 + f];
    float4 xr1 = x4[row * 16 + 8 + f];
    float  bv  = beta[0];
    float  bs  = bv * g_inv[row];         // beta / ||x_r||

    float4 acc0 = make_float4(0.f, 0.f, 0.f, 0.f);
    float4 acc1 = make_float4(0.f, 0.f, 0.f, 0.f);
    float  wsum = 0.f;

    const int*   __restrict__ col = g_col;
    const float* __restrict__ inv = g_inv;

    int nIter = (n + 3) >> 2;             // 4 edges per iteration
    #pragma unroll 2
    for (int it = 0; it < nIter; ++it) {
        int  e     = (it << 2) + g;
        bool valid = e < n;
        int  c     = col[valid ? s + e : s];   // broadcast load (8 lanes/group)
        float invnc = inv[c];                  // scalar gather, hoistable

        float4 b0 = x4[c * 16 + f];
        float4 b1 = x4[c * 16 + 8 + f];

        float d = b0.x * xr0.x + b0.y * xr0.y + b0.z * xr0.z + b0.w * xr0.w
                + b1.x * xr1.x + b1.y * xr1.y + b1.z * xr1.z + b1.w * xr1.w;
        d += __shfl_xor_sync(FULL, d, 1);
        d += __shfl_xor_sync(FULL, d, 2);
        d += __shfl_xor_sync(FULL, d, 4);

        float w = __expf(fmaf(bs * invnc, d, -bv));  // exp(beta*(cos-1)) <= 1
        w = valid ? w : 0.f;

        wsum  += w;
        acc0.x = fmaf(w, b0.x, acc0.x);
        acc0.y = fmaf(w, b0.y, acc0.y);
        acc0.z = fmaf(w, b0.z, acc0.z);
        acc0.w = fmaf(w, b0.w, acc0.w);
        acc1.x = fmaf(w, b1.x, acc1.x);
        acc1.y = fmaf(w, b1.y, acc1.y);
        acc1.z = fmaf(w, b1.z, acc1.z);
        acc1.w = fmaf(w, b1.w, acc1.w);
    }

    // reduce the 4 edge-groups (butterfly -> all lanes hold totals)
    #pragma unroll
    for (int o = 8; o <= 16; o <<= 1) {
        acc0.x += __shfl_xor_sync(FULL, acc0.x, o);
        acc0.y += __shfl_xor_sync(FULL, acc0.y, o);
        acc0.z += __shfl_xor_sync(FULL, acc0.z, o);
        acc0.w += __shfl_xor_sync(FULL, acc0.w, o);
        acc1.x += __shfl_xor_sync(FULL, acc1.x, o);
        acc1.y += __shfl_xor_sync(FULL, acc1.y, o);
        acc1.z += __shfl_xor_sync(FULL, acc1.z, o);
        acc1.w += __shfl_xor_sync(FULL, acc1.w, o);
        wsum   += __shfl_xor_sync(FULL, wsum,   o);
    }

    if (g == 0) {
        float invw = (n > 0) ? (1.f / wsum) : 0.f;
        out4[row * 16 + f]     = make_float4(acc0.x * invw, acc0.y * invw,
                                             acc0.z * invw, acc0.w * invw);
        out4[row * 16 + 8 + f] = make_float4(acc1.x * invw, acc1.y * invw,
                                             acc1.z * invw, acc1.w * invw);
    }
}

// ---------------------------------------------------------------------------
extern "C" void kernel_launch(void* const* d_in, const int* in_sizes, int n_in,
                              void* d_out, int out_size)
{
    const float4* x    = 0;
    const float*  beta = 0;
    const void*   er   = 0;
    const void*   ec   = 0;
    for (int i = 0; i < n_in; ++i) {
        long long sz = in_sizes[i];
        if (sz == (long long)N_NODES * D_FEAT) x = (const float4*)d_in[i];
        else if (sz == 1)                      beta = (const float*)d_in[i];
        else if (sz == N_EDGES) {
            if (!er) er = d_in[i]; else ec = d_in[i];
        }
    }
    float4* out = (float4*)d_out;

    prep_kernel<<<B_NORM + B_COL + B_ROW, 256>>>(x, er, ec);

    {   // one warp per row
        long long total = (long long)N_NODES * 32;
        int blocks = (int)((total + 255) / 256);
        fused_row_kernel<<<blocks, 256>>>(x, beta, out);
    }
}